// round 1
// baseline (speedup 1.0000x reference)
#include <cuda_runtime.h>
#include <math.h>

#define N_NODES 100000
#define E_EDGES 1200000
#define EPS 1e-5f

// -------- scratch (device globals; no allocation allowed) --------
__device__ float g_A[N_NODES * 64];   // layer input / BN output
__device__ float g_B[N_NODES * 64];   // h = x @ W
__device__ float g_C[N_NODES * 64];   // scatter accumulator
__device__ float g_dinv[N_NODES];
__device__ float g_norm[E_EDGES];
__device__ int   g_deg[N_NODES];
__device__ float g_stats[128];        // [0..63] sum, [64..127] sumsq

// ----------------- degree / norm precompute -----------------
__global__ void k_deg_init(int* deg, int n) {
    int i = blockIdx.x * blockDim.x + threadIdx.x;
    if (i < n) deg[i] = 1;  // self loop
}

__global__ void k_deg_count(const int* __restrict__ dst, int* deg, int e) {
    int i = blockIdx.x * blockDim.x + threadIdx.x;
    if (i < e) atomicAdd(&deg[dst[i]], 1);
}

__global__ void k_dinv(const int* __restrict__ deg, float* dinv, int n) {
    int i = blockIdx.x * blockDim.x + threadIdx.x;
    if (i < n) dinv[i] = 1.0f / sqrtf((float)deg[i]);
}

__global__ void k_norm(const int* __restrict__ src, const int* __restrict__ dst,
                       const float* __restrict__ dinv, float* norm, int e) {
    int i = blockIdx.x * blockDim.x + threadIdx.x;
    if (i < e) norm[i] = dinv[src[i]] * dinv[dst[i]];
}

__global__ void k_zero_stats(float* stats) {
    int i = threadIdx.x;
    if (i < 128) stats[i] = 0.0f;
}

// ----------------- fused GEMM + self-loop init -----------------
// h = x @ W ; C = b + dinv^2 * h
template <int FIN, int FOUT>
__global__ void k_gemm_init(const float* __restrict__ x, const float* __restrict__ W,
                            const float* __restrict__ b, const float* __restrict__ dinv,
                            float* __restrict__ h, float* __restrict__ outc, int n) {
    __shared__ float sW[FIN * FOUT];
    __shared__ float sb[FOUT];
    for (int i = threadIdx.x; i < FIN * FOUT; i += blockDim.x) sW[i] = W[i];
    for (int i = threadIdx.x; i < FOUT; i += blockDim.x) sb[i] = b[i];
    __syncthreads();
    int node = blockIdx.x * blockDim.x + threadIdx.x;
    if (node >= n) return;
    float xv[FIN];
#pragma unroll
    for (int k = 0; k < FIN; k++) xv[k] = x[node * FIN + k];
    float di = dinv[node];
    float di2 = di * di;
#pragma unroll 4
    for (int j = 0; j < FOUT; j++) {
        float acc = 0.0f;
#pragma unroll
        for (int k = 0; k < FIN; k++) acc = fmaf(xv[k], sW[k * FOUT + j], acc);
        h[node * FOUT + j] = acc;
        outc[node * FOUT + j] = sb[j] + di2 * acc;
    }
}

// ----------------- edge scatter (atomic) -----------------
template <int F>
__global__ void k_scatter(const float* __restrict__ h, const int* __restrict__ src,
                          const int* __restrict__ dst, const float* __restrict__ norm,
                          float* __restrict__ outc, int e) {
    constexpr int Q = F / 4;  // float4 chunks per edge
    int idx = blockIdx.x * blockDim.x + threadIdx.x;
    if (idx >= e * Q) return;
    int eidx = idx / Q;
    int q = idx - eidx * Q;
    int s = __ldg(&src[eidx]);
    int d = __ldg(&dst[eidx]);
    float nv = __ldg(&norm[eidx]);
    const float4 hv = *reinterpret_cast<const float4*>(h + (size_t)s * F + q * 4);
    float* po = outc + (size_t)d * F + q * 4;
    atomicAdd(po + 0, hv.x * nv);
    atomicAdd(po + 1, hv.y * nv);
    atomicAdd(po + 2, hv.z * nv);
    atomicAdd(po + 3, hv.w * nv);
}

// ----------------- relu + per-feature sum/sumsq -----------------
template <int F>
__global__ void k_stats(const float* __restrict__ c, float* __restrict__ stats, int n) {
    __shared__ float ss[256];
    __shared__ float sq[256];
    int tid = threadIdx.x;
    long total = (long)n * F;
    long stride = (long)blockDim.x * gridDim.x;  // multiple of F (F divides 256)
    float s = 0.0f, s2 = 0.0f;
    for (long i = (long)blockIdx.x * blockDim.x + tid; i < total; i += stride) {
        float v = fmaxf(c[i], 0.0f);
        s += v;
        s2 += v * v;
    }
    ss[tid] = s;
    sq[tid] = s2;
    __syncthreads();
    for (int off = 128; off >= F; off >>= 1) {
        if (tid < off) {
            ss[tid] += ss[tid + off];
            sq[tid] += sq[tid + off];
        }
        __syncthreads();
    }
    if (tid < F) {
        atomicAdd(&stats[tid], ss[tid]);
        atomicAdd(&stats[64 + tid], sq[tid]);
    }
}

// ----------------- relu + BN + ELU -----------------
template <int F>
__global__ void k_bn_elu(const float* __restrict__ c, const float* __restrict__ stats,
                         const float* __restrict__ g, const float* __restrict__ bt,
                         float* __restrict__ out, int n) {
    long idx = (long)blockIdx.x * blockDim.x + threadIdx.x;
    if (idx >= (long)n * F) return;
    int col = (int)(idx % F);
    float inv_n = 1.0f / (float)n;
    float mean = stats[col] * inv_n;
    float var = stats[64 + col] * inv_n - mean * mean;
    float v = fmaxf(c[idx], 0.0f);
    float y = (v - mean) * rsqrtf(var + EPS) * g[col] + bt[col];
    out[idx] = (y > 0.0f) ? y : expm1f(y);
}

// ----------------- fused MLP + log_softmax -----------------
__global__ void __launch_bounds__(128)
k_mlp(const float* __restrict__ h,
      const float* __restrict__ Wf1, const float* __restrict__ bf1,
      const float* __restrict__ Wf2, const float* __restrict__ bf2,
      const float* __restrict__ Wf3, const float* __restrict__ bf3,
      float* __restrict__ out, int n) {
    __shared__ float sW1[64 * 32], sb1[32];
    __shared__ float sW2[32 * 16], sb2[16];
    __shared__ float sW3[16 * 2], sb3[2];
    for (int i = threadIdx.x; i < 64 * 32; i += blockDim.x) sW1[i] = Wf1[i];
    for (int i = threadIdx.x; i < 32 * 16; i += blockDim.x) sW2[i] = Wf2[i];
    for (int i = threadIdx.x; i < 32; i += blockDim.x) sW3[i] = Wf3[i];
    if (threadIdx.x < 32) sb1[threadIdx.x] = bf1[threadIdx.x];
    if (threadIdx.x < 16) sb2[threadIdx.x] = bf2[threadIdx.x];
    if (threadIdx.x < 2) sb3[threadIdx.x] = bf3[threadIdx.x];
    __syncthreads();
    int node = blockIdx.x * blockDim.x + threadIdx.x;
    if (node >= n) return;

    float x[64];
    const float4* hp = reinterpret_cast<const float4*>(h + (size_t)node * 64);
#pragma unroll
    for (int k = 0; k < 16; k++) {
        float4 v = hp[k];
        x[k * 4 + 0] = v.x;
        x[k * 4 + 1] = v.y;
        x[k * 4 + 2] = v.z;
        x[k * 4 + 3] = v.w;
    }

    float t1[32];
#pragma unroll 4
    for (int j = 0; j < 32; j++) {
        float acc = sb1[j];
#pragma unroll
        for (int k = 0; k < 64; k++) acc = fmaf(x[k], sW1[k * 32 + j], acc);
        t1[j] = (acc > 0.0f) ? acc : expm1f(acc);
    }

    float t2[16];
#pragma unroll 4
    for (int j = 0; j < 16; j++) {
        float acc = sb2[j];
#pragma unroll
        for (int k = 0; k < 32; k++) acc = fmaf(t1[k], sW2[k * 16 + j], acc);
        t2[j] = (acc > 0.0f) ? acc : expm1f(acc);
    }

    float o0 = sb3[0], o1 = sb3[1];
#pragma unroll
    for (int k = 0; k < 16; k++) {
        o0 = fmaf(t2[k], sW3[k * 2 + 0], o0);
        o1 = fmaf(t2[k], sW3[k * 2 + 1], o1);
    }
    float m = fmaxf(o0, o1);
    float lse = m + logf(expf(o0 - m) + expf(o1 - m));
    out[node * 2 + 0] = o0 - lse;
    out[node * 2 + 1] = o1 - lse;
}

// ----------------- launch -----------------
extern "C" void kernel_launch(void* const* d_in, const int* in_sizes, int n_in,
                              void* d_out, int out_size) {
    const float* x   = (const float*)d_in[0];
    const int* eidx  = (const int*)d_in[1];
    const float* W1  = (const float*)d_in[2];
    const float* b1  = (const float*)d_in[3];
    const float* g1  = (const float*)d_in[4];
    const float* bt1 = (const float*)d_in[5];
    const float* W2  = (const float*)d_in[6];
    const float* b2  = (const float*)d_in[7];
    const float* g2  = (const float*)d_in[8];
    const float* bt2 = (const float*)d_in[9];
    const float* W3  = (const float*)d_in[10];
    const float* b3  = (const float*)d_in[11];
    const float* g3  = (const float*)d_in[12];
    const float* bt3 = (const float*)d_in[13];
    const float* Wf1 = (const float*)d_in[14];
    const float* bf1 = (const float*)d_in[15];
    const float* Wf2 = (const float*)d_in[16];
    const float* bf2 = (const float*)d_in[17];
    const float* Wf3 = (const float*)d_in[18];
    const float* bf3 = (const float*)d_in[19];
    float* out = (float*)d_out;

    const int n = in_sizes[0] / 4;
    const int e = in_sizes[1] / 2;
    const int* src = eidx;
    const int* dst = eidx + e;

    float *pA, *pB, *pC, *pDinv, *pNorm, *pStats;
    int* pDeg;
    cudaGetSymbolAddress((void**)&pA, g_A);
    cudaGetSymbolAddress((void**)&pB, g_B);
    cudaGetSymbolAddress((void**)&pC, g_C);
    cudaGetSymbolAddress((void**)&pDinv, g_dinv);
    cudaGetSymbolAddress((void**)&pNorm, g_norm);
    cudaGetSymbolAddress((void**)&pStats, g_stats);
    cudaGetSymbolAddress((void**)&pDeg, g_deg);

    const int TB = 256;
    const int gn = (n + TB - 1) / TB;
    const int ge = (e + TB - 1) / TB;

    // degree / norm
    k_deg_init<<<gn, TB>>>(pDeg, n);
    k_deg_count<<<ge, TB>>>(dst, pDeg, e);
    k_dinv<<<gn, TB>>>(pDeg, pDinv, n);
    k_norm<<<ge, TB>>>(src, dst, pDinv, pNorm, e);

    const int STATS_BLOCKS = 1184;

    // ---- layer 1: 4 -> 16 ----
    {
        constexpr int F = 16;
        k_gemm_init<4, F><<<gn, TB>>>(x, W1, b1, pDinv, pB, pC, n);
        int gs = (e * (F / 4) + TB - 1) / TB;
        k_scatter<F><<<gs, TB>>>(pB, src, dst, pNorm, pC, e);
        k_zero_stats<<<1, 128>>>(pStats);
        k_stats<F><<<STATS_BLOCKS, TB>>>(pC, pStats, n);
        int gel = (n * F + TB - 1) / TB;
        k_bn_elu<F><<<gel, TB>>>(pC, pStats, g1, bt1, pA, n);
    }
    // ---- layer 2: 16 -> 32 ----
    {
        constexpr int F = 32;
        k_gemm_init<16, F><<<gn, TB>>>(pA, W2, b2, pDinv, pB, pC, n);
        int gs = (e * (F / 4) + TB - 1) / TB;
        k_scatter<F><<<gs, TB>>>(pB, src, dst, pNorm, pC, e);
        k_zero_stats<<<1, 128>>>(pStats);
        k_stats<F><<<STATS_BLOCKS, TB>>>(pC, pStats, n);
        int gel = (n * F + TB - 1) / TB;
        k_bn_elu<F><<<gel, TB>>>(pC, pStats, g2, bt2, pA, n);
    }
    // ---- layer 3: 32 -> 64 ----
    {
        constexpr int F = 64;
        k_gemm_init<32, F><<<gn, TB>>>(pA, W3, b3, pDinv, pB, pC, n);
        int gs = (e * (F / 4) + TB - 1) / TB;
        k_scatter<F><<<gs, TB>>>(pB, src, dst, pNorm, pC, e);
        k_zero_stats<<<1, 128>>>(pStats);
        k_stats<F><<<STATS_BLOCKS, TB>>>(pC, pStats, n);
        int gel = (n * F + TB - 1) / TB;
        k_bn_elu<F><<<gel, TB>>>(pC, pStats, g3, bt3, pA, n);
    }

    // ---- MLP head + log_softmax ----
    k_mlp<<<(n + 127) / 128, 128>>>(pA, Wf1, bf1, Wf2, bf2, Wf3, bf3, out, n);
}